// round 3
// baseline (speedup 1.0000x reference)
#include <cuda_runtime.h>
#include <math.h>

// ---------------------------------------------------------------------------
// Problem constants
// ---------------------------------------------------------------------------
#define NB     16
#define CQ     512
#define HW     64          // H == W == 64
#define CV     1024
#define INNER  512
#define NT     65536       // total q tokens: 16 * 16*16 * 16
#define NC     4096        // total cells:   16 * 16*16
#define LN_EPS 1e-5f
#define SCL    0.044194173824159216f   // 512^-0.5

// ---------------------------------------------------------------------------
// Scratch: static device globals (allocation APIs are forbidden).
// buf0: qn -> X ; buf1: Q -> pre-residual out ; vn ; V
// Referenced DIRECTLY from device code — kernel_launch does no symbol lookups.
// ---------------------------------------------------------------------------
__device__ float g_buf0[(size_t)NT * INNER];
__device__ float g_buf1[(size_t)NT * INNER];
__device__ float g_vn  [(size_t)NC * CV];
__device__ float g_V   [(size_t)NC * INNER];

// ---------------------------------------------------------------------------
// Packed f32x2 helpers (PTX ISA 8.6+, sm_100+: 2x fp32 FMA throughput)
// ---------------------------------------------------------------------------
__device__ __forceinline__ unsigned long long pk2(float lo, float hi) {
    unsigned long long r;
    asm("mov.b64 %0, {%1, %2};" : "=l"(r) : "f"(lo), "f"(hi));
    return r;
}
__device__ __forceinline__ void upk2(unsigned long long v, float& lo, float& hi) {
    asm("mov.b64 {%0, %1}, %2;" : "=f"(lo), "=f"(hi) : "l"(v));
}
__device__ __forceinline__ unsigned long long ffma2(unsigned long long a,
                                                    unsigned long long b,
                                                    unsigned long long c) {
    unsigned long long d;
    asm("fma.rn.f32x2 %0, %1, %2, %3;" : "=l"(d) : "l"(a), "l"(b), "l"(c));
    return d;
}

// ---------------------------------------------------------------------------
// K1: q LayerNorm + gather into token-major g_buf0[t][512]
// One CTA per (batch, pixel-row, 16-column group): 16 tokens x 512 channels.
// token t = (((b*16+gh)*16+gw)*16) + py*4 + px ; row = gh*4+py, col = gw*4+px
// Static SMEM: 512*17*4 = 34,816 B (< 48 KB, no opt-in needed).
// ---------------------------------------------------------------------------
__global__ void __launch_bounds__(256)
qln_kernel(const float* __restrict__ q,
           const float* __restrict__ gamma,
           const float* __restrict__ beta) {
    __shared__ float s[512 * 17];
    __shared__ float mu[16], rs[16];
    int tid  = threadIdx.x;
    int blk  = blockIdx.x;               // 16*64*4 = 4096 blocks
    int bb   = blk >> 8;
    int rem  = blk & 255;
    int row  = rem >> 2;                 // 0..63  (gh*4+py)
    int quad = rem & 3;                  // 16-column group
    int gh   = row >> 2, py = row & 3;

    const float* qrow = q + ((size_t)bb * CQ) * 4096 + (size_t)row * 64 + quad * 16;
    for (int idx = tid; idx < CQ * 16; idx += 256) {
        int c = idx >> 4, x = idx & 15;  // 64B-coalesced along W
        s[c * 17 + x] = qrow[(size_t)c * 4096 + x];
    }
    __syncthreads();

    int x = tid >> 4, j = tid & 15;      // 16 threads reduce one token
    float sum = 0.f, ss = 0.f;
    for (int c = j; c < CQ; c += 16) {
        float v = s[c * 17 + x];
        sum += v; ss += v * v;
    }
#pragma unroll
    for (int off = 8; off >= 1; off >>= 1) {
        sum += __shfl_down_sync(0xffffffffu, sum, off, 16);
        ss  += __shfl_down_sync(0xffffffffu, ss,  off, 16);
    }
    if (j == 0) {
        float mean = sum * (1.f / CQ);
        float var  = ss  * (1.f / CQ) - mean * mean;
        mu[x] = mean;
        rs[x] = rsqrtf(var + LN_EPS);
    }
    __syncthreads();

    for (int idx = tid; idx < CQ * 16; idx += 256) {
        int c = idx & 511, xx = idx >> 9;     // coalesced along c in output
        int gw = quad * 4 + (xx >> 2), px = xx & 3;
        int t  = ((bb * 16 + gh) * 16 + gw) * 16 + py * 4 + px;
        g_buf0[(size_t)t * INNER + c] =
            (s[c * 17 + xx] - mu[xx]) * rs[xx] * gamma[c] + beta[c];
    }
}

// ---------------------------------------------------------------------------
// K2: v LayerNorm into cell-major g_vn[cell][1024].
// One CTA per (b, gh, gw-half): 8 cells. Static SMEM 1024*9*4 = 36,864 B.
// ---------------------------------------------------------------------------
__global__ void __launch_bounds__(256)
vln_kernel(const float* __restrict__ v,
           const float* __restrict__ gamma,
           const float* __restrict__ beta) {
    __shared__ float s[1024 * 9];
    __shared__ float mu[8], rs[8];
    int tid  = threadIdx.x;
    int blk  = blockIdx.x;               // 16*16*2 = 512 blocks
    int bb   = blk >> 5;
    int rem  = blk & 31;
    int gh   = rem >> 1;
    int half = rem & 1;

    const float* vrow = v + ((size_t)bb * CV) * 256 + gh * 16 + half * 8;
    for (int idx = tid; idx < CV * 8; idx += 256) {
        int c = idx >> 3, gw = idx & 7;
        s[c * 9 + gw] = vrow[(size_t)c * 256 + gw];
    }
    __syncthreads();

    int gwi = tid >> 5, j = tid & 31;    // one warp per cell
    float sum = 0.f, ss = 0.f;
    for (int c = j; c < CV; c += 32) {
        float vv = s[c * 9 + gwi];
        sum += vv; ss += vv * vv;
    }
#pragma unroll
    for (int off = 16; off >= 1; off >>= 1) {
        sum += __shfl_down_sync(0xffffffffu, sum, off, 32);
        ss  += __shfl_down_sync(0xffffffffu, ss,  off, 32);
    }
    if (j == 0) {
        float mean = sum * (1.f / CV);
        float var  = ss  * (1.f / CV) - mean * mean;
        mu[gwi] = mean;
        rs[gwi] = rsqrtf(var + LN_EPS);
    }
    __syncthreads();

    int cellbase = (bb * 16 + gh) * 16 + half * 8;
    for (int idx = tid; idx < CV * 8; idx += 256) {
        int c = idx & 1023, gw = idx >> 10;
        g_vn[(size_t)(cellbase + gw) * CV + c] =
            (s[c * 9 + gw] - mu[gw]) * rs[gw] * gamma[c] + beta[c];
    }
}

// ---------------------------------------------------------------------------
// Tiled NT GEMM:  C[m,n] = sum_k A[m,k] * W[n,k]  (+ epilogue), N fixed = 512.
// BM=BN=128, BK=16, 256 threads, 8x8 micro-tile in packed f32x2 accumulators.
// MODE 0: C = acc + bias[n]
// MODE 1: C = sigmoid(acc * SCL) * g_V[m>>4][n]     (no bias)
// A / C scratch buffers chosen by runtime selector (0=buf0, 1=buf1, 2=vn, 3=V)
// Static SMEM: 2*(2*16*132*4) = 33,792 B.
// ---------------------------------------------------------------------------
#define BM  128
#define BN  128
#define BK  16
#define LDP 132   // BM + 4 padding (bank-conflict relief)

__device__ __forceinline__ float* buf_sel(int sel) {
    return sel == 0 ? g_buf0 : sel == 1 ? g_buf1 : sel == 2 ? g_vn : g_V;
}

template<int MODE>
__global__ void __launch_bounds__(256)
gemm_nt_kernel(int asel, const float* __restrict__ W,
               const float* __restrict__ bias, int csel, int K) {
    __shared__ __align__(16) float As[2][BK][LDP];
    __shared__ __align__(16) float Ws[2][BK][LDP];

    const float* A = buf_sel(asel);
    float*       C = buf_sel(csel);

    int tid = threadIdx.x;
    int n0  = blockIdx.x * BN;     // n-tile fastest: A tiles reused in-wave
    int m0  = blockIdx.y * BM;

    int lr = tid >> 2, lc = tid & 3;
    const float* Ap = A + (size_t)(m0 + lr) * K + lc * 4;
    const float* Wp = W + (size_t)(n0 + lr) * K + lc * 4;
    size_t rowoff = (size_t)64 * K;

    float4 ra0 = *(const float4*)(Ap);
    float4 ra1 = *(const float4*)(Ap + rowoff);
    float4 rw0 = *(const float4*)(Wp);
    float4 rw1 = *(const float4*)(Wp + rowoff);

    unsigned long long acc[8][4];
#pragma unroll
    for (int i = 0; i < 8; i++)
#pragma unroll
        for (int jj = 0; jj < 4; jj++) acc[i][jj] = 0ull;

    {   // stage 0 (transposed: As[k][m])
        float* as = &As[0][0][0];
        float* ws = &Ws[0][0][0];
        as[(lc*4+0)*LDP + lr]      = ra0.x; as[(lc*4+1)*LDP + lr]      = ra0.y;
        as[(lc*4+2)*LDP + lr]      = ra0.z; as[(lc*4+3)*LDP + lr]      = ra0.w;
        as[(lc*4+0)*LDP + lr + 64] = ra1.x; as[(lc*4+1)*LDP + lr + 64] = ra1.y;
        as[(lc*4+2)*LDP + lr + 64] = ra1.z; as[(lc*4+3)*LDP + lr + 64] = ra1.w;
        ws[(lc*4+0)*LDP + lr]      = rw0.x; ws[(lc*4+1)*LDP + lr]      = rw0.y;
        ws[(lc*4+2)*LDP + lr]      = rw0.z; ws[(lc*4+3)*LDP + lr]      = rw0.w;
        ws[(lc*4+0)*LDP + lr + 64] = rw1.x; ws[(lc*4+1)*LDP + lr + 64] = rw1.y;
        ws[(lc*4+2)*LDP + lr + 64] = rw1.z; ws[(lc*4+3)*LDP + lr + 64] = rw1.w;
    }
    __syncthreads();

    int tx = tid & 15, ty = tid >> 4;
    int nt = K / BK;
    for (int t = 0; t < nt; t++) {
        int st = t & 1;
        if (t + 1 < nt) {                       // prefetch next tile into regs
            const float* Ap2 = Ap + (size_t)(t + 1) * BK;
            const float* Wp2 = Wp + (size_t)(t + 1) * BK;
            ra0 = *(const float4*)(Ap2);
            ra1 = *(const float4*)(Ap2 + rowoff);
            rw0 = *(const float4*)(Wp2);
            rw1 = *(const float4*)(Wp2 + rowoff);
        }
#pragma unroll
        for (int k = 0; k < BK; k++) {
            float4 af0 = *(const float4*)&As[st][k][ty * 8];
            float4 af1 = *(const float4*)&As[st][k][ty * 8 + 4];
            float4 wf0 = *(const float4*)&Ws[st][k][tx * 8];
            float4 wf1 = *(const float4*)&Ws[st][k][tx * 8 + 4];
            unsigned long long b2[4] = { pk2(wf0.x, wf0.y), pk2(wf0.z, wf0.w),
                                         pk2(wf1.x, wf1.y), pk2(wf1.z, wf1.w) };
            float a[8] = {af0.x, af0.y, af0.z, af0.w, af1.x, af1.y, af1.z, af1.w};
#pragma unroll
            for (int i = 0; i < 8; i++) {
                unsigned long long aa = pk2(a[i], a[i]);
#pragma unroll
                for (int jj = 0; jj < 4; jj++)
                    acc[i][jj] = ffma2(aa, b2[jj], acc[i][jj]);
            }
        }
        if (t + 1 < nt) {
            int s2 = st ^ 1;
            float* as = &As[s2][0][0];
            float* ws = &Ws[s2][0][0];
            as[(lc*4+0)*LDP + lr]      = ra0.x; as[(lc*4+1)*LDP + lr]      = ra0.y;
            as[(lc*4+2)*LDP + lr]      = ra0.z; as[(lc*4+3)*LDP + lr]      = ra0.w;
            as[(lc*4+0)*LDP + lr + 64] = ra1.x; as[(lc*4+1)*LDP + lr + 64] = ra1.y;
            as[(lc*4+2)*LDP + lr + 64] = ra1.z; as[(lc*4+3)*LDP + lr + 64] = ra1.w;
            ws[(lc*4+0)*LDP + lr]      = rw0.x; ws[(lc*4+1)*LDP + lr]      = rw0.y;
            ws[(lc*4+2)*LDP + lr]      = rw0.z; ws[(lc*4+3)*LDP + lr]      = rw0.w;
            ws[(lc*4+0)*LDP + lr + 64] = rw1.x; ws[(lc*4+1)*LDP + lr + 64] = rw1.y;
            ws[(lc*4+2)*LDP + lr + 64] = rw1.z; ws[(lc*4+3)*LDP + lr + 64] = rw1.w;
            __syncthreads();
        }
    }

    // epilogue
    int nb = n0 + tx * 8;
    float4 e0, e1;
    if (MODE == 0) {
        e0 = *(const float4*)&bias[nb];
        e1 = *(const float4*)&bias[nb + 4];
    } else {
        int cell = (m0 + ty * 8) >> 4;           // constant across micro-rows
        e0 = *(const float4*)&g_V[(size_t)cell * INNER + nb];
        e1 = *(const float4*)&g_V[(size_t)cell * INNER + nb + 4];
    }
#pragma unroll
    for (int i = 0; i < 8; i++) {
        int m = m0 + ty * 8 + i;
        float c0, c1, c2, c3, c4, c5, c6, c7;
        upk2(acc[i][0], c0, c1); upk2(acc[i][1], c2, c3);
        upk2(acc[i][2], c4, c5); upk2(acc[i][3], c6, c7);
        float4 o0, o1;
        if (MODE == 0) {
            o0 = make_float4(c0 + e0.x, c1 + e0.y, c2 + e0.z, c3 + e0.w);
            o1 = make_float4(c4 + e1.x, c5 + e1.y, c6 + e1.z, c7 + e1.w);
        } else {
            o0.x = e0.x / (1.f + __expf(-c0 * SCL));
            o0.y = e0.y / (1.f + __expf(-c1 * SCL));
            o0.z = e0.z / (1.f + __expf(-c2 * SCL));
            o0.w = e0.w / (1.f + __expf(-c3 * SCL));
            o1.x = e1.x / (1.f + __expf(-c4 * SCL));
            o1.y = e1.y / (1.f + __expf(-c5 * SCL));
            o1.z = e1.z / (1.f + __expf(-c6 * SCL));
            o1.w = e1.w / (1.f + __expf(-c7 * SCL));
        }
        *(float4*)&C[(size_t)m * INNER + nb]     = o0;
        *(float4*)&C[(size_t)m * INNER + nb + 4] = o1;
    }
}

// ---------------------------------------------------------------------------
// K7: residual + scatter g_buf1[t][CQ] back to NCHW out[B, CQ, 64, 64]
// Mirror of K1 tiling. Static SMEM 34,816 B.
// ---------------------------------------------------------------------------
__global__ void __launch_bounds__(256)
scatter_kernel(const float* __restrict__ q, float* __restrict__ out) {
    __shared__ float s[512 * 17];
    int tid  = threadIdx.x;
    int blk  = blockIdx.x;               // 4096 blocks
    int bb   = blk >> 8;
    int rem  = blk & 255;
    int row  = rem >> 2;
    int quad = rem & 3;
    int gh   = row >> 2, py = row & 3;

    for (int idx = tid; idx < CQ * 16; idx += 256) {
        int c = idx & 511, x = idx >> 9;      // coalesced read along c
        int gw = quad * 4 + (x >> 2), px = x & 3;
        int t  = ((bb * 16 + gh) * 16 + gw) * 16 + py * 4 + px;
        s[c * 17 + x] = g_buf1[(size_t)t * INNER + c];
    }
    __syncthreads();

    size_t base = ((size_t)bb * CQ) * 4096 + (size_t)row * 64 + quad * 16;
    for (int idx = tid; idx < CQ * 16; idx += 256) {
        int c = idx >> 4, x = idx & 15;       // 64B-coalesced along W
        size_t addr = base + (size_t)c * 4096 + x;
        out[addr] = q[addr] + s[c * 17 + x];
    }
}

// ---------------------------------------------------------------------------
// launch — kernel launches ONLY (no attribute/symbol/alloc/sync API calls)
// ---------------------------------------------------------------------------
extern "C" void kernel_launch(void* const* d_in, const int* in_sizes, int n_in,
                              void* d_out, int out_size) {
    (void)in_sizes; (void)n_in; (void)out_size;
    const float* q   = (const float*)d_in[0];
    const float* v   = (const float*)d_in[1];
    const float* qng = (const float*)d_in[2];
    const float* qnb = (const float*)d_in[3];
    const float* vng = (const float*)d_in[4];
    const float* vnb = (const float*)d_in[5];
    const float* qpw = (const float*)d_in[6];
    const float* qpb = (const float*)d_in[7];
    const float* vpw = (const float*)d_in[8];
    const float* vpb = (const float*)d_in[9];
    const float* cm  = (const float*)d_in[10];
    const float* ow  = (const float*)d_in[11];
    const float* ob  = (const float*)d_in[12];
    float* out = (float*)d_out;

    // 1) g_buf0 = LN(q), token-major
    qln_kernel<<<NB * HW * 4, 256>>>(q, qng, qnb);
    // 2) g_vn = LN(v), cell-major
    vln_kernel<<<NB * 16 * 2, 256>>>(v, vng, vnb);
    // 3) g_V = vn @ Wv^T + bv      [4096, 512]
    gemm_nt_kernel<0><<<dim3(4, 32),  256>>>(2, vpw, vpb, 3, CV);
    // 4) g_buf1 = qn @ Wq^T + bq   [65536, 512]
    gemm_nt_kernel<0><<<dim3(4, 512), 256>>>(0, qpw, qpb, 1, INNER);
    // 5) g_buf0 = sigmoid(Q @ CM^T * scl) * V
    gemm_nt_kernel<1><<<dim3(4, 512), 256>>>(1, cm, (const float*)nullptr, 0, INNER);
    // 6) g_buf1 = X @ Wo^T + bo
    gemm_nt_kernel<0><<<dim3(4, 512), 256>>>(0, ow, ob, 1, INNER);
    // 7) out = q + scatter(g_buf1)
    scatter_kernel<<<NB * HW * 4, 256>>>(q, out);
}

// round 5
// speedup vs baseline: 3.5291x; 3.5291x over previous
#include <cuda_runtime.h>
#include <cuda_bf16.h>
#include <math.h>
#include <stdint.h>

// ---------------------------------------------------------------------------
// Problem constants
// ---------------------------------------------------------------------------
#define NB     16
#define CQ     512
#define HW     64
#define CV     1024
#define INNER  512
#define NT     65536       // q tokens
#define NC     4096        // cells
#define LN_EPS 1e-5f
#define SCL    0.044194173824159216f   // 512^-0.5

// ---------------------------------------------------------------------------
// Scratch (static device globals; referenced directly from device code)
// ---------------------------------------------------------------------------
__device__ __nv_bfloat16 g_qnb[(size_t)NT * INNER];   // LN(q), token-major
__device__ __nv_bfloat16 g_Qb [(size_t)NT * INNER];   // Q projection
__device__ __nv_bfloat16 g_Xb [(size_t)NT * INNER];   // attn * V
__device__ __nv_bfloat16 g_vnb[(size_t)NC * CV];      // LN(v), cell-major
__device__ float         g_V  [(size_t)NC * INNER];   // V projection (fp32)
__device__ float         g_O  [(size_t)NT * INNER];   // pre-residual out (fp32)
__device__ __nv_bfloat16 g_wq [(size_t)INNER * CQ];
__device__ __nv_bfloat16 g_wv [(size_t)INNER * CV];
__device__ __nv_bfloat16 g_wcm[(size_t)INNER * INNER];
__device__ __nv_bfloat16 g_wo [(size_t)CQ * INNER];

__device__ __forceinline__ const __nv_bfloat16* a_sel(int s) {
    return s == 0 ? g_qnb : s == 1 ? g_Qb : s == 2 ? g_Xb : g_vnb;
}
__device__ __forceinline__ __nv_bfloat16* w_sel(int s) {
    return s == 0 ? g_wq : s == 1 ? g_wv : s == 2 ? g_wcm : g_wo;
}
__device__ __forceinline__ __nv_bfloat16* bf_out_sel(int s) {
    return s == 0 ? g_Qb : g_Xb;
}
__device__ __forceinline__ float* f_out_sel(int s) {
    return s == 0 ? g_V : g_O;
}

// ---------------------------------------------------------------------------
// Base-ISA helpers (valid on compute_100): cp.async, ldmatrix, mma.sync
// ---------------------------------------------------------------------------
__device__ __forceinline__ uint32_t smem_u32(const void* p) {
    uint32_t a;
    asm("{ .reg .u64 t; cvta.to.shared.u64 t, %1; cvt.u32.u64 %0, t; }"
        : "=r"(a) : "l"(p));
    return a;
}
__device__ __forceinline__ void cpasync16(uint32_t s, const void* g) {
    asm volatile("cp.async.cg.shared.global [%0], [%1], 16;" :: "r"(s), "l"(g));
}
__device__ __forceinline__ void cp_commit() {
    asm volatile("cp.async.commit_group;" ::: "memory");
}
__device__ __forceinline__ void cp_wait1() {
    asm volatile("cp.async.wait_group 1;" ::: "memory");
}
__device__ __forceinline__ void ldmx4(uint32_t* r, uint32_t addr) {
    asm volatile("ldmatrix.sync.aligned.m8n8.x4.shared.b16 {%0,%1,%2,%3}, [%4];"
                 : "=r"(r[0]), "=r"(r[1]), "=r"(r[2]), "=r"(r[3]) : "r"(addr));
}
__device__ __forceinline__ void ldmx2(uint32_t* r, uint32_t addr) {
    asm volatile("ldmatrix.sync.aligned.m8n8.x2.shared.b16 {%0,%1}, [%2];"
                 : "=r"(r[0]), "=r"(r[1]) : "r"(addr));
}
__device__ __forceinline__ void mma16816(float* c, const uint32_t* a, const uint32_t* b) {
    asm volatile(
        "mma.sync.aligned.m16n8k16.row.col.f32.bf16.bf16.f32 "
        "{%0,%1,%2,%3}, {%4,%5,%6,%7}, {%8,%9}, {%0,%1,%2,%3};"
        : "+f"(c[0]), "+f"(c[1]), "+f"(c[2]), "+f"(c[3])
        : "r"(a[0]), "r"(a[1]), "r"(a[2]), "r"(a[3]), "r"(b[0]), "r"(b[1]));
}

// ---------------------------------------------------------------------------
// HMMA GEMM:  C[m,n] = sum_k A[m,k] * W[n,k]  (+ epilogue).  N total = 512.
// BM=BN=128, BK=32, 256 threads (8 warps, 2m x 4n, warp tile 64x32).
// SMEM rows at 80B stride (conflict-free ldmatrix). 2-stage cp.async pipeline.
// MODE 0: bf16 out = acc + bias      MODE 1: bf16 out = sigmoid(acc*SCL)*V[m>>4]
// MODE 2: f32  out = acc + bias
// Static SMEM: 2 stages x (A 10240B + B 10240B) = 40 KB.
// ---------------------------------------------------------------------------
#define RSTR 80   // smem row stride in bytes (4 x 16B chunks + 16B pad)

template<int MODE>
__global__ void __launch_bounds__(256)
hmma_gemm_kernel(int aSel, int wSel, const float* __restrict__ bias,
                 int cSel, int K) {
    __shared__ __align__(16) unsigned char As[2][128 * RSTR];
    __shared__ __align__(16) unsigned char Bs[2][128 * RSTR];

    const __nv_bfloat16* A = a_sel(aSel);
    const __nv_bfloat16* W = w_sel(wSel);

    int tid = threadIdx.x;
    int wid = tid >> 5, lid = tid & 31;
    int m0  = blockIdx.y * 128;
    int n0  = blockIdx.x * 128;
    int wm  = wid & 1;          // 2 m-groups of 64
    int wn  = wid >> 1;         // 4 n-groups of 32

    uint32_t asm0 = smem_u32(As[0]);
    uint32_t bsm0 = smem_u32(Bs[0]);

    // ---- load geometry: thread t covers row=t>>1, chunk pair (t&1)*2 ----
    int lrow = tid >> 1, lcp = (tid & 1) * 2;
    const __nv_bfloat16* aG = A + (size_t)(m0 + lrow) * K + lcp * 8;
    const __nv_bfloat16* wG = W + (size_t)(n0 + lrow) * K + lcp * 8;
    uint32_t aS = asm0 + lrow * RSTR + lcp * 16;
    uint32_t bS = bsm0 + lrow * RSTR + lcp * 16;

    int nt = K >> 5;
    // prologue: stage 0, stage 1
#pragma unroll
    for (int p = 0; p < 2; p++) {
        const __nv_bfloat16* ag = aG + p * 32;
        const __nv_bfloat16* wg = wG + p * 32;
        uint32_t as = aS + p * (128 * RSTR);
        uint32_t bs = bS + p * (128 * RSTR);
        cpasync16(as, ag);       cpasync16(as + 16, ag + 8);
        cpasync16(bs, wg);       cpasync16(bs + 16, wg + 8);
        cp_commit();
    }

    float acc[4][4][4];
#pragma unroll
    for (int i = 0; i < 4; i++)
#pragma unroll
        for (int j = 0; j < 4; j++)
#pragma unroll
            for (int e = 0; e < 4; e++) acc[i][j][e] = 0.f;

    // ldmatrix address components (per-lane)
    uint32_t aRow = wm * 64 + (lid & 15);     // + mi*16
    uint32_t aChk = (lid >> 4);               // + ks*2
    uint32_t bRow = wn * 32 + (lid & 7);      // + ni*8
    uint32_t bChk = ((lid >> 3) & 1);         // + ks*2

    for (int t = 0; t < nt; t++) {
        cp_wait1();
        __syncthreads();

        int st = t & 1;
        uint32_t ab = asm0 + st * (128 * RSTR);
        uint32_t bb = bsm0 + st * (128 * RSTR);
#pragma unroll
        for (int ks = 0; ks < 2; ks++) {
            uint32_t a[4][4], b[4][2];
#pragma unroll
            for (int mi = 0; mi < 4; mi++)
                ldmx4(a[mi], ab + (aRow + mi * 16) * RSTR + (aChk + ks * 2) * 16);
#pragma unroll
            for (int ni = 0; ni < 4; ni++)
                ldmx2(b[ni], bb + (bRow + ni * 8) * RSTR + (bChk + ks * 2) * 16);
#pragma unroll
            for (int mi = 0; mi < 4; mi++)
#pragma unroll
                for (int ni = 0; ni < 4; ni++)
                    mma16816(acc[mi][ni], a[mi], b[ni]);
        }
        __syncthreads();

        if (t + 2 < nt) {
            const __nv_bfloat16* ag = aG + (size_t)(t + 2) * 32;
            const __nv_bfloat16* wg = wG + (size_t)(t + 2) * 32;
            uint32_t as = aS + st * (128 * RSTR);
            uint32_t bs = bS + st * (128 * RSTR);
            cpasync16(as, ag);       cpasync16(as + 16, ag + 8);
            cpasync16(bs, wg);       cpasync16(bs + 16, wg + 8);
        }
        cp_commit();
    }

    // ---- epilogue ----
    // c0,c1: row r, cols n,n+1 ; c2,c3: row r+8, same cols (r = lid>>2)
    int r  = lid >> 2;
    int cl = (lid & 3) * 2;
#pragma unroll
    for (int mi = 0; mi < 4; mi++) {
        int mb = m0 + wm * 64 + mi * 16;
#pragma unroll
        for (int ni = 0; ni < 4; ni++) {
            int n = n0 + wn * 32 + ni * 8 + cl;
            float v0 = acc[mi][ni][0], v1 = acc[mi][ni][1];
            float v2 = acc[mi][ni][2], v3 = acc[mi][ni][3];
            if (MODE == 0) {
                float2 bv = *(const float2*)&bias[n];
                v0 += bv.x; v1 += bv.y; v2 += bv.x; v3 += bv.y;
                __nv_bfloat16* Cb = bf_out_sel(cSel);
                *(__nv_bfloat162*)(Cb + (size_t)(mb + r) * 512 + n) =
                    __floats2bfloat162_rn(v0, v1);
                *(__nv_bfloat162*)(Cb + (size_t)(mb + r + 8) * 512 + n) =
                    __floats2bfloat162_rn(v2, v3);
            } else if (MODE == 1) {
                int cell = mb >> 4;   // constant over the 16 rows of this mi
                float2 vv = *(const float2*)&g_V[(size_t)cell * 512 + n];
                v0 = vv.x / (1.f + __expf(-v0 * SCL));
                v1 = vv.y / (1.f + __expf(-v1 * SCL));
                v2 = vv.x / (1.f + __expf(-v2 * SCL));
                v3 = vv.y / (1.f + __expf(-v3 * SCL));
                __nv_bfloat16* Cb = bf_out_sel(cSel);
                *(__nv_bfloat162*)(Cb + (size_t)(mb + r) * 512 + n) =
                    __floats2bfloat162_rn(v0, v1);
                *(__nv_bfloat162*)(Cb + (size_t)(mb + r + 8) * 512 + n) =
                    __floats2bfloat162_rn(v2, v3);
            } else {
                float2 bv = *(const float2*)&bias[n];
                float* Cf = f_out_sel(cSel);
                *(float2*)(Cf + (size_t)(mb + r) * 512 + n) =
                    make_float2(v0 + bv.x, v1 + bv.y);
                *(float2*)(Cf + (size_t)(mb + r + 8) * 512 + n) =
                    make_float2(v2 + bv.x, v3 + bv.y);
            }
        }
    }
}

// ---------------------------------------------------------------------------
// K1: q LayerNorm + gather -> g_qnb (bf16, token-major)
// ---------------------------------------------------------------------------
__global__ void __launch_bounds__(256)
qln_kernel(const float* __restrict__ q,
           const float* __restrict__ gamma,
           const float* __restrict__ beta) {
    __shared__ float s[512 * 17];
    __shared__ float mu[16], rs[16];
    int tid  = threadIdx.x;
    int blk  = blockIdx.x;               // 4096 blocks
    int bb   = blk >> 8;
    int rem  = blk & 255;
    int row  = rem >> 2;
    int quad = rem & 3;
    int gh   = row >> 2, py = row & 3;

    const float* qrow = q + ((size_t)bb * CQ) * 4096 + (size_t)row * 64 + quad * 16;
    for (int idx = tid; idx < CQ * 16; idx += 256) {
        int c = idx >> 4, x = idx & 15;
        s[c * 17 + x] = qrow[(size_t)c * 4096 + x];
    }
    __syncthreads();

    int x = tid >> 4, j = tid & 15;
    float sum = 0.f, ss = 0.f;
    for (int c = j; c < CQ; c += 16) {
        float v = s[c * 17 + x];
        sum += v; ss += v * v;
    }
#pragma unroll
    for (int off = 8; off >= 1; off >>= 1) {
        sum += __shfl_down_sync(0xffffffffu, sum, off, 16);
        ss  += __shfl_down_sync(0xffffffffu, ss,  off, 16);
    }
    if (j == 0) {
        float mean = sum * (1.f / CQ);
        float var  = ss  * (1.f / CQ) - mean * mean;
        mu[x] = mean;
        rs[x] = rsqrtf(var + LN_EPS);
    }
    __syncthreads();

    for (int idx = tid; idx < 16 * 256; idx += 256) {
        int xx = idx >> 8;
        int c  = (idx & 255) * 2;
        int gw = quad * 4 + (xx >> 2), px = xx & 3;
        int t  = ((bb * 16 + gh) * 16 + gw) * 16 + py * 4 + px;
        float a0 = (s[c * 17 + xx]       - mu[xx]) * rs[xx] * gamma[c]     + beta[c];
        float a1 = (s[(c + 1) * 17 + xx] - mu[xx]) * rs[xx] * gamma[c + 1] + beta[c + 1];
        *(__nv_bfloat162*)(g_qnb + (size_t)t * 512 + c) = __floats2bfloat162_rn(a0, a1);
    }
}

// ---------------------------------------------------------------------------
// K2: v LayerNorm -> g_vnb (bf16, cell-major)
// ---------------------------------------------------------------------------
__global__ void __launch_bounds__(256)
vln_kernel(const float* __restrict__ v,
           const float* __restrict__ gamma,
           const float* __restrict__ beta) {
    __shared__ float s[1024 * 9];
    __shared__ float mu[8], rs[8];
    int tid  = threadIdx.x;
    int blk  = blockIdx.x;               // 512 blocks
    int bb   = blk >> 5;
    int rem  = blk & 31;
    int gh   = rem >> 1;
    int half = rem & 1;

    const float* vrow = v + ((size_t)bb * CV) * 256 + gh * 16 + half * 8;
    for (int idx = tid; idx < CV * 8; idx += 256) {
        int c = idx >> 3, gw = idx & 7;
        s[c * 9 + gw] = vrow[(size_t)c * 256 + gw];
    }
    __syncthreads();

    int gwi = tid >> 5, j = tid & 31;
    float sum = 0.f, ss = 0.f;
    for (int c = j; c < CV; c += 32) {
        float vv = s[c * 9 + gwi];
        sum += vv; ss += vv * vv;
    }
#pragma unroll
    for (int off = 16; off >= 1; off >>= 1) {
        sum += __shfl_down_sync(0xffffffffu, sum, off, 32);
        ss  += __shfl_down_sync(0xffffffffu, ss,  off, 32);
    }
    if (j == 0) {
        float mean = sum * (1.f / CV);
        float var  = ss  * (1.f / CV) - mean * mean;
        mu[gwi] = mean;
        rs[gwi] = rsqrtf(var + LN_EPS);
    }
    __syncthreads();

    int cellbase = (bb * 16 + gh) * 16 + half * 8;
    for (int idx = tid; idx < 8 * 512; idx += 256) {
        int xx = idx >> 9;
        int c  = (idx & 511) * 2;
        float a0 = (s[c * 9 + xx]       - mu[xx]) * rs[xx] * gamma[c]     + beta[c];
        float a1 = (s[(c + 1) * 9 + xx] - mu[xx]) * rs[xx] * gamma[c + 1] + beta[c + 1];
        *(__nv_bfloat162*)(g_vnb + (size_t)(cellbase + xx) * CV + c) =
            __floats2bfloat162_rn(a0, a1);
    }
}

// ---------------------------------------------------------------------------
// Weight conversion f32 -> bf16
// ---------------------------------------------------------------------------
__global__ void f2b_kernel(const float* __restrict__ in, int wSel, int n2) {
    int i = blockIdx.x * blockDim.x + threadIdx.x;
    if (i < n2) {
        float2 f = ((const float2*)in)[i];
        ((__nv_bfloat162*)w_sel(wSel))[i] = __floats2bfloat162_rn(f.x, f.y);
    }
}

// ---------------------------------------------------------------------------
// K7: residual + scatter g_O (fp32) back to NCHW out
// ---------------------------------------------------------------------------
__global__ void __launch_bounds__(256)
scatter_kernel(const float* __restrict__ q, float* __restrict__ out) {
    __shared__ float s[512 * 17];
    int tid  = threadIdx.x;
    int blk  = blockIdx.x;
    int bb   = blk >> 8;
    int rem  = blk & 255;
    int row  = rem >> 2;
    int quad = rem & 3;
    int gh   = row >> 2, py = row & 3;

    for (int idx = tid; idx < CQ * 16; idx += 256) {
        int c = idx & 511, x = idx >> 9;
        int gw = quad * 4 + (x >> 2), px = x & 3;
        int t  = ((bb * 16 + gh) * 16 + gw) * 16 + py * 4 + px;
        s[c * 17 + x] = g_O[(size_t)t * 512 + c];
    }
    __syncthreads();

    size_t base = ((size_t)bb * CQ) * 4096 + (size_t)row * 64 + quad * 16;
    for (int idx = tid; idx < CQ * 16; idx += 256) {
        int c = idx >> 4, x = idx & 15;
        size_t addr = base + (size_t)c * 4096 + x;
        out[addr] = q[addr] + s[c * 17 + x];
    }
}

// ---------------------------------------------------------------------------
// launch — kernel launches ONLY
// ---------------------------------------------------------------------------
extern "C" void kernel_launch(void* const* d_in, const int* in_sizes, int n_in,
                              void* d_out, int out_size) {
    (void)in_sizes; (void)n_in; (void)out_size;
    const float* q   = (const float*)d_in[0];
    const float* v   = (const float*)d_in[1];
    const float* qng = (const float*)d_in[2];
    const float* qnb = (const float*)d_in[3];
    const float* vng = (const float*)d_in[4];
    const float* vnb = (const float*)d_in[5];
    const float* qpw = (const float*)d_in[6];
    const float* qpb = (const float*)d_in[7];
    const float* vpw = (const float*)d_in[8];
    const float* vpb = (const float*)d_in[9];
    const float* cm  = (const float*)d_in[10];
    const float* ow  = (const float*)d_in[11];
    const float* ob  = (const float*)d_in[12];
    float* out = (float*)d_out;

    // 1) LayerNorms -> bf16
    qln_kernel<<<NB * HW * 4, 256>>>(q, qng, qnb);
    vln_kernel<<<NB * 16 * 2, 256>>>(v, vng, vnb);
    // 2) weights -> bf16
    f2b_kernel<<<512,  256>>>(qpw, 0, INNER * CQ / 2);
    f2b_kernel<<<1024, 256>>>(vpw, 1, INNER * CV / 2);
    f2b_kernel<<<512,  256>>>(cm,  2, INNER * INNER / 2);
    f2b_kernel<<<512,  256>>>(ow,  3, CQ * INNER / 2);
    // 3) V = vn @ Wv^T + bv  (fp32 out)     [4096, 512], K=1024
    hmma_gemm_kernel<2><<<dim3(4, 32), 256>>>(3, 1, vpb, 0, CV);
    // 4) Q = qn @ Wq^T + bq  (bf16 out)     [65536, 512]
    hmma_gemm_kernel<0><<<dim3(4, 512), 256>>>(0, 0, qpb, 0, INNER);
    // 5) X = sigmoid(Q @ CM^T * scl) * V  (bf16 out)
    hmma_gemm_kernel<1><<<dim3(4, 512), 256>>>(1, 2, qpb, 1, INNER);
    // 6) O = X @ Wo^T + bo  (fp32 out)
    hmma_gemm_kernel<2><<<dim3(4, 512), 256>>>(2, 3, ob, 1, INNER);
    // 7) out = q + scatter(O)
    scatter_kernel<<<NB * HW * 4, 256>>>(q, out);
}